// round 1
// baseline (speedup 1.0000x reference)
#include <cuda_runtime.h>
#include <math.h>

#define NTOK 8192          // B*S = 4*2048
#define DM 1024            // D_MODEL
#define DE 512             // D_EXPERT
#define NE 8               // N_EXPERTS

// ---- scratch (device globals; no runtime allocation) ----
__device__ int   g_count[NE];
__device__ int   g_tok [NE * NTOK];
__device__ float g_gate[NE * NTOK];
__device__ float g_h   [(size_t)NE * NTOK * DE];   // 128 MiB gelu(h) buffer

// ============================================================
// 0) zero output + counters
// ============================================================
__global__ void zero_kernel(float* __restrict__ out) {
    int idx = blockIdx.x * blockDim.x + threadIdx.x;   // 8192*256 threads, 4 floats each
    float4 z = make_float4(0.f, 0.f, 0.f, 0.f);
    ((float4*)out)[idx] = z;
    if (blockIdx.x == 0 && threadIdx.x < NE) g_count[threadIdx.x] = 0;
}

// ============================================================
// 1) routing: one warp per token
// ============================================================
__global__ void route_kernel(const float* __restrict__ x,
                             const float* __restrict__ centroids,
                             const float* __restrict__ w_route) {
    int gwarp = (blockIdx.x * blockDim.x + threadIdx.x) >> 5;
    int lane  = threadIdx.x & 31;
    if (gwarp >= NTOK) return;
    int tok = gwarp;

    const float4* xr = (const float4*)(x + (size_t)tok * DM);
    float4 xv[8];
#pragma unroll
    for (int u = 0; u < 8; u++) xv[u] = xr[u * 32 + lane];

    // ||x||^2
    float nx = 0.f;
#pragma unroll
    for (int u = 0; u < 8; u++) {
        float4 v = xv[u];
        nx += v.x * v.x + v.y * v.y + v.z * v.z + v.w * v.w;
    }
#pragma unroll
    for (int off = 16; off; off >>= 1) nx += __shfl_xor_sync(0xffffffffu, nx, off);
    float xn = fmaxf(sqrtf(nx), 1e-12f);

    float logits[NE];
#pragma unroll
    for (int e = 0; e < NE; e++) {
        const float4* cr = (const float4*)(centroids + (size_t)e * DM);
        const float4* wr = (const float4*)(w_route   + (size_t)e * DM);
        float sc = 0.f, scc = 0.f, sr = 0.f;
#pragma unroll
        for (int u = 0; u < 8; u++) {
            float4 c = cr[u * 32 + lane];
            float4 w = wr[u * 32 + lane];
            float4 v = xv[u];
            sc  += v.x * c.x + v.y * c.y + v.z * c.z + v.w * c.w;
            scc += c.x * c.x + c.y * c.y + c.z * c.z + c.w * c.w;
            sr  += v.x * w.x + v.y * w.y + v.z * w.z + v.w * w.w;
        }
#pragma unroll
        for (int off = 16; off; off >>= 1) {
            sc  += __shfl_xor_sync(0xffffffffu, sc,  off);
            scc += __shfl_xor_sync(0xffffffffu, scc, off);
            sr  += __shfl_xor_sync(0xffffffffu, sr,  off);
        }
        float cn = fmaxf(sqrtf(scc), 1e-12f);
        logits[e] = sc / (xn * cn) + sr;
    }

    if (lane == 0) {
        int e1 = 0; float l1 = logits[0];
#pragma unroll
        for (int e = 1; e < NE; e++) if (logits[e] > l1) { l1 = logits[e]; e1 = e; }
        int e2 = -1; float l2 = -INFINITY;
#pragma unroll
        for (int e = 0; e < NE; e++) if (e != e1 && logits[e] > l2) { l2 = logits[e]; e2 = e; }
        // softmax over {l1, l2}, l1 >= l2
        float b  = expf(l2 - l1);
        float g1 = 1.f / (1.f + b);
        float g2 = b  / (1.f + b);
        int p1 = atomicAdd(&g_count[e1], 1);
        g_tok [e1 * NTOK + p1] = tok;
        g_gate[e1 * NTOK + p1] = g1;
        int p2 = atomicAdd(&g_count[e2], 1);
        g_tok [e2 * NTOK + p2] = tok;
        g_gate[e2 * NTOK + p2] = g2;
    }
}

// ============================================================
// shared GEMM tile constants: 128x128x16 per block, 256 thr, 8x8/thread
// ============================================================
#define BM 128
#define BN 128
#define BK 16
#define TM 8
#define TN 8

// ============================================================
// 2) FF1: h = gelu(gather(x) @ w1[e] + b1[e])   (K=DM, N=DE)
// ============================================================
__global__ __launch_bounds__(256) void ff1_kernel(const float* __restrict__ x,
                                                  const float* __restrict__ w1,
                                                  const float* __restrict__ b1) {
    int e   = blockIdx.z;
    int cnt = g_count[e];
    int m0  = blockIdx.x * BM;
    if (m0 >= cnt) return;
    int n0  = blockIdx.y * BN;

    __shared__ float As[BK][BM + 4];
    __shared__ float Bs[BK][BN];
    __shared__ int   rows[BM];

    int tid = threadIdx.x;
    if (tid < BM) {
        int m = m0 + tid;
        rows[tid] = (m < cnt) ? g_tok[e * NTOK + m] : -1;
    }
    __syncthreads();

    float acc[TM][TN];
#pragma unroll
    for (int i = 0; i < TM; i++)
#pragma unroll
        for (int j = 0; j < TN; j++) acc[i][j] = 0.f;

    int tx = tid & 15, ty = tid >> 4;
    int a_row = tid >> 2, a_c = tid & 3;       // 64 rows x 4 k-chunks, x2 passes
    int b_row = tid >> 5, b_c = tid & 31;      // 8 k-rows x 32 n-chunks, x2 passes

    const float* w1e = w1 + (size_t)e * DM * DE;

    for (int k0 = 0; k0 < DM; k0 += BK) {
#pragma unroll
        for (int r = 0; r < 2; r++) {
            int i   = a_row + r * 64;
            int row = rows[i];
            float4 v = make_float4(0.f, 0.f, 0.f, 0.f);
            if (row >= 0)
                v = *(const float4*)(x + (size_t)row * DM + k0 + a_c * 4);
            As[a_c * 4 + 0][i] = v.x;
            As[a_c * 4 + 1][i] = v.y;
            As[a_c * 4 + 2][i] = v.z;
            As[a_c * 4 + 3][i] = v.w;
        }
#pragma unroll
        for (int r = 0; r < 2; r++) {
            int kk = b_row + r * 8;
            *(float4*)&Bs[kk][b_c * 4] =
                *(const float4*)(w1e + (size_t)(k0 + kk) * DE + n0 + b_c * 4);
        }
        __syncthreads();
#pragma unroll
        for (int kk = 0; kk < BK; kk++) {
            float ra[TM], rb[TN];
            *(float4*)&ra[0] = *(const float4*)&As[kk][ty * TM];
            *(float4*)&ra[4] = *(const float4*)&As[kk][ty * TM + 4];
            *(float4*)&rb[0] = *(const float4*)&Bs[kk][tx * TN];
            *(float4*)&rb[4] = *(const float4*)&Bs[kk][tx * TN + 4];
#pragma unroll
            for (int i = 0; i < TM; i++)
#pragma unroll
                for (int j = 0; j < TN; j++) acc[i][j] += ra[i] * rb[j];
        }
        __syncthreads();
    }

#pragma unroll
    for (int i = 0; i < TM; i++) {
        int m = m0 + ty * TM + i;
        if (m >= cnt) continue;
        float* hrow = g_h + ((size_t)e * NTOK + m) * DE + n0;
#pragma unroll
        for (int j = 0; j < TN; j++) {
            int n = tx * TN + j;
            float v = acc[i][j] + b1[e * DE + n0 + n];
            v = 0.5f * v * (1.0f + erff(v * 0.7071067811865476f));
            hrow[n] = v;
        }
    }
}

// ============================================================
// 3) FF2: out[tok] += gate * (h @ w2[e] + b2[e])   (K=DE, N=DM)
// ============================================================
__global__ __launch_bounds__(256) void ff2_kernel(const float* __restrict__ w2,
                                                  const float* __restrict__ b2,
                                                  float* __restrict__ out) {
    int e   = blockIdx.z;
    int cnt = g_count[e];
    int m0  = blockIdx.x * BM;
    if (m0 >= cnt) return;
    int n0  = blockIdx.y * BN;

    __shared__ float As[BK][BM + 4];
    __shared__ float Bs[BK][BN];

    int tid = threadIdx.x;
    int tx = tid & 15, ty = tid >> 4;
    int a_row = tid >> 2, a_c = tid & 3;
    int b_row = tid >> 5, b_c = tid & 31;

    float acc[TM][TN];
#pragma unroll
    for (int i = 0; i < TM; i++)
#pragma unroll
        for (int j = 0; j < TN; j++) acc[i][j] = 0.f;

    const float* w2e   = w2 + (size_t)e * DE * DM;
    const float* hbase = g_h + (size_t)e * NTOK * DE;

    for (int k0 = 0; k0 < DE; k0 += BK) {
#pragma unroll
        for (int r = 0; r < 2; r++) {
            int i = a_row + r * 64;
            int m = m0 + i;
            float4 v = make_float4(0.f, 0.f, 0.f, 0.f);
            if (m < cnt)
                v = *(const float4*)(hbase + (size_t)m * DE + k0 + a_c * 4);
            As[a_c * 4 + 0][i] = v.x;
            As[a_c * 4 + 1][i] = v.y;
            As[a_c * 4 + 2][i] = v.z;
            As[a_c * 4 + 3][i] = v.w;
        }
#pragma unroll
        for (int r = 0; r < 2; r++) {
            int kk = b_row + r * 8;
            *(float4*)&Bs[kk][b_c * 4] =
                *(const float4*)(w2e + (size_t)(k0 + kk) * DM + n0 + b_c * 4);
        }
        __syncthreads();
#pragma unroll
        for (int kk = 0; kk < BK; kk++) {
            float ra[TM], rb[TN];
            *(float4*)&ra[0] = *(const float4*)&As[kk][ty * TM];
            *(float4*)&ra[4] = *(const float4*)&As[kk][ty * TM + 4];
            *(float4*)&rb[0] = *(const float4*)&Bs[kk][tx * TN];
            *(float4*)&rb[4] = *(const float4*)&Bs[kk][tx * TN + 4];
#pragma unroll
            for (int i = 0; i < TM; i++)
#pragma unroll
                for (int j = 0; j < TN; j++) acc[i][j] += ra[i] * rb[j];
        }
        __syncthreads();
    }

#pragma unroll
    for (int i = 0; i < TM; i++) {
        int m = m0 + ty * TM + i;
        if (m >= cnt) continue;
        int   tok = g_tok [e * NTOK + m];
        float g   = g_gate[e * NTOK + m];
        float* orow = out + (size_t)tok * DM + n0;
#pragma unroll
        for (int j = 0; j < TN; j++) {
            int n = tx * TN + j;
            atomicAdd(&orow[n], g * (acc[i][j] + b2[e * DM + n0 + n]));
        }
    }
}

// ============================================================
// launcher
// ============================================================
extern "C" void kernel_launch(void* const* d_in, const int* in_sizes, int n_in,
                              void* d_out, int out_size) {
    const float* x         = (const float*)d_in[0];
    const float* w1        = (const float*)d_in[1];
    const float* b1        = (const float*)d_in[2];
    const float* w2        = (const float*)d_in[3];
    const float* b2        = (const float*)d_in[4];
    const float* centroids = (const float*)d_in[5];
    const float* w_route   = (const float*)d_in[6];
    float* out = (float*)d_out;

    zero_kernel <<<(NTOK * DM) / (256 * 4), 256>>>(out);
    route_kernel<<<NTOK / 4, 128>>>(x, centroids, w_route);
    ff1_kernel  <<<dim3(NTOK / BM, DE / BN, NE), 256>>>(x, w1, b1);
    ff2_kernel  <<<dim3(NTOK / BM, DM / BN, NE), 256>>>(w2, b2, out);
}

// round 6
// speedup vs baseline: 2.1513x; 2.1513x over previous
#include <cuda_runtime.h>
#include <cuda_bf16.h>
#include <stdint.h>
#include <math.h>

#define NTOK 8192          // B*S
#define DM 1024
#define DE 512
#define NE 8

// ---------------- scratch (device globals) ----------------
__device__ int   g_count[NE];
__device__ int   g_tok [NE * NTOK];
__device__ float g_gate[NE * NTOK];
__device__ __nv_bfloat16 g_x_hi[(size_t)NTOK * DM];
__device__ __nv_bfloat16 g_x_lo[(size_t)NTOK * DM];
__device__ __nv_bfloat16 g_h_hi[(size_t)NE * NTOK * DE];
__device__ __nv_bfloat16 g_h_lo[(size_t)NE * NTOK * DE];
__device__ __nv_bfloat16 g_w1t_hi[(size_t)NE * DE * DM];   // [e][n][k] k-major
__device__ __nv_bfloat16 g_w1t_lo[(size_t)NE * DE * DM];
__device__ __nv_bfloat16 g_w2t_hi[(size_t)NE * DM * DE];   // [e][n][k]
__device__ __nv_bfloat16 g_w2t_lo[(size_t)NE * DM * DE];

// ---------------- helpers ----------------
static __device__ __forceinline__ uint32_t smem_u32(const void* p) {
    uint32_t a;
    asm("{ .reg .u64 t; cvta.to.shared.u64 t, %1; cvt.u32.u64 %0, t; }"
        : "=r"(a) : "l"(p));
    return a;
}

static __device__ __forceinline__ void cpa16(uint32_t dst, const void* src) {
    asm volatile("cp.async.cg.shared.global [%0], [%1], 16;" :: "r"(dst), "l"(src));
}
#define CP_COMMIT() asm volatile("cp.async.commit_group;" ::: "memory")
#define CP_WAIT1()  asm volatile("cp.async.wait_group 1;" ::: "memory")

#define LDMX4(r0, r1, r2, r3, addr)                                          \
    asm volatile("ldmatrix.sync.aligned.m8n8.x4.shared.b16 {%0,%1,%2,%3}, [%4];" \
        : "=r"(r0), "=r"(r1), "=r"(r2), "=r"(r3) : "r"(addr))

#define MMA(ac, a, b)                                                        \
    asm volatile("mma.sync.aligned.m16n8k16.row.col.f32.bf16.bf16.f32 "      \
        "{%0,%1,%2,%3}, {%4,%5,%6,%7}, {%8,%9}, {%0,%1,%2,%3};"              \
        : "+f"((ac)[0]), "+f"((ac)[1]), "+f"((ac)[2]), "+f"((ac)[3])         \
        : "r"((a)[0]), "r"((a)[1]), "r"((a)[2]), "r"((a)[3]),                \
          "r"((b)[0]), "r"((b)[1]))

static __device__ __forceinline__ void split1(float v, unsigned& h, unsigned& l) {
    __nv_bfloat16 bh = __float2bfloat16_rn(v);
    float r = v - __bfloat162float(bh);
    __nv_bfloat16 bl = __float2bfloat16_rn(r);
    h = (unsigned)__bfloat16_as_ushort(bh);
    l = (unsigned)__bfloat16_as_ushort(bl);
}

// ============================================================
// 0) zero output + counters
// ============================================================
__global__ void zero_kernel(float* __restrict__ out) {
    int idx = blockIdx.x * blockDim.x + threadIdx.x;
    ((float4*)out)[idx] = make_float4(0.f, 0.f, 0.f, 0.f);
    if (blockIdx.x == 0 && threadIdx.x < NE) g_count[threadIdx.x] = 0;
}

// ============================================================
// 1) routing: one warp per token
// ============================================================
__global__ void route_kernel(const float* __restrict__ x,
                             const float* __restrict__ centroids,
                             const float* __restrict__ w_route) {
    int gwarp = (blockIdx.x * blockDim.x + threadIdx.x) >> 5;
    int lane  = threadIdx.x & 31;
    if (gwarp >= NTOK) return;
    int tok = gwarp;

    const float4* xr = (const float4*)(x + (size_t)tok * DM);
    float4 xv[8];
#pragma unroll
    for (int u = 0; u < 8; u++) xv[u] = xr[u * 32 + lane];

    float nx = 0.f;
#pragma unroll
    for (int u = 0; u < 8; u++) {
        float4 v = xv[u];
        nx += v.x * v.x + v.y * v.y + v.z * v.z + v.w * v.w;
    }
#pragma unroll
    for (int off = 16; off; off >>= 1) nx += __shfl_xor_sync(0xffffffffu, nx, off);
    float xn = fmaxf(sqrtf(nx), 1e-12f);

    float logits[NE];
#pragma unroll
    for (int e = 0; e < NE; e++) {
        const float4* cr = (const float4*)(centroids + (size_t)e * DM);
        const float4* wr = (const float4*)(w_route   + (size_t)e * DM);
        float sc = 0.f, scc = 0.f, sr = 0.f;
#pragma unroll
        for (int u = 0; u < 8; u++) {
            float4 c = cr[u * 32 + lane];
            float4 w = wr[u * 32 + lane];
            float4 v = xv[u];
            sc  += v.x * c.x + v.y * c.y + v.z * c.z + v.w * c.w;
            scc += c.x * c.x + c.y * c.y + c.z * c.z + c.w * c.w;
            sr  += v.x * w.x + v.y * w.y + v.z * w.z + v.w * w.w;
        }
#pragma unroll
        for (int off = 16; off; off >>= 1) {
            sc  += __shfl_xor_sync(0xffffffffu, sc,  off);
            scc += __shfl_xor_sync(0xffffffffu, scc, off);
            sr  += __shfl_xor_sync(0xffffffffu, sr,  off);
        }
        float cn = fmaxf(sqrtf(scc), 1e-12f);
        logits[e] = sc / (xn * cn) + sr;
    }

    if (lane == 0) {
        int e1 = 0; float l1 = logits[0];
#pragma unroll
        for (int e = 1; e < NE; e++) if (logits[e] > l1) { l1 = logits[e]; e1 = e; }
        int e2 = -1; float l2 = -INFINITY;
#pragma unroll
        for (int e = 0; e < NE; e++) if (e != e1 && logits[e] > l2) { l2 = logits[e]; e2 = e; }
        float b  = expf(l2 - l1);
        float g1 = 1.f / (1.f + b);
        float g2 = b  / (1.f + b);
        int p1 = atomicAdd(&g_count[e1], 1);
        g_tok [e1 * NTOK + p1] = tok;
        g_gate[e1 * NTOK + p1] = g1;
        int p2 = atomicAdd(&g_count[e2], 1);
        g_tok [e2 * NTOK + p2] = tok;
        g_gate[e2 * NTOK + p2] = g2;
    }
}

// ============================================================
// 2) prep: split x -> bf16 hi/lo
// ============================================================
__global__ void prep_x_kernel(const float* __restrict__ x) {
    size_t i = (size_t)blockIdx.x * blockDim.x + threadIdx.x;   // float4 index
    float4 v = ((const float4*)x)[i];
    unsigned h0, l0, h1, l1, h2, l2, h3, l3;
    split1(v.x, h0, l0); split1(v.y, h1, l1);
    split1(v.z, h2, l2); split1(v.w, h3, l3);
    ((uint2*)g_x_hi)[i] = make_uint2(h0 | (h1 << 16), h2 | (h3 << 16));
    ((uint2*)g_x_lo)[i] = make_uint2(l0 | (l1 << 16), l2 | (l3 << 16));
}

// ============================================================
// 3) weight prep: transpose [e][K][N] -> [e][N][K] + bf16 hi/lo split
// ============================================================
static __device__ __forceinline__ void transpose_split_body(
    const float* __restrict__ in, __nv_bfloat16* __restrict__ ohi,
    __nv_bfloat16* __restrict__ olo, int K, int N)
{
    __shared__ float t[32][33];
    int e  = blockIdx.z;
    int n0 = blockIdx.x * 32, k0 = blockIdx.y * 32;
    const float* pin = in + (size_t)e * K * N;
#pragma unroll
    for (int i = 0; i < 4; i++)
        t[threadIdx.y + i * 8][threadIdx.x] =
            pin[(size_t)(k0 + threadIdx.y + i * 8) * N + n0 + threadIdx.x];
    __syncthreads();
#pragma unroll
    for (int i = 0; i < 4; i++) {
        int nl = threadIdx.y + i * 8, kl = threadIdx.x;
        unsigned h, l; split1(t[kl][nl], h, l);
        size_t o = ((size_t)e * N + n0 + nl) * K + k0 + kl;
        ohi[o] = __ushort_as_bfloat16((unsigned short)h);
        olo[o] = __ushort_as_bfloat16((unsigned short)l);
    }
}

__global__ void prep_w1_kernel(const float* __restrict__ w1) {
    transpose_split_body(w1, g_w1t_hi, g_w1t_lo, DM, DE);
}
__global__ void prep_w2_kernel(const float* __restrict__ w2) {
    transpose_split_body(w2, g_w2t_hi, g_w2t_lo, DE, DM);
}

// ============================================================
// GEMM geometry: block 128x128, BK=64, 8 warps (2x4), warp 64x32
// smem row: 64 bf16 data + 8 pad = 72 elems = 144 B
// ============================================================
#define BK 64
#define SROWB 144
#define TILE_B (128 * SROWB)          // 18432 B per buffer
#define STAGE_B (4 * TILE_B)          // Ahi Alo Bhi Blo
#define DYN_SMEM (2 * STAGE_B)        // 147456 B

// ============================================================
// 4) FF1: h = gelu(gather(x) @ w1[e] + b1[e])
//    grid (NTOK/128, DE/128, NE), block 256
// ============================================================
__global__ __launch_bounds__(256, 1) void ff1_mma(const float* __restrict__ b1) {
    extern __shared__ char dsm[];
    __shared__ int rows_s[128];

    int e   = blockIdx.z;
    int cnt = g_count[e];
    int m0  = blockIdx.x * 128;
    if (m0 >= cnt) return;
    int n0  = blockIdx.y * 128;
    int tid = threadIdx.x, lane = tid & 31, wid = tid >> 5;
    int warpM = wid >> 2, warpN = wid & 3;

    if (tid < 128) {
        int m = m0 + tid;
        rows_s[tid] = (m < cnt) ? g_tok[e * NTOK + m] : 0;
    }
    __syncthreads();

    uint32_t sbase = smem_u32(dsm);

    // per-lane ldmatrix offsets
    int arow = lane & 15;
    int akad = (lane >> 4) << 3;           // 0 / 8
    int brow = ((lane & 16) >> 1) | (lane & 7);
    int bkad = lane & 8;                   // 0 / 8
    uint32_t a_off = (uint32_t)((warpM * 64 + arow) * SROWB + akad * 2);
    uint32_t b_off = (uint32_t)((warpN * 32 + brow) * SROWB + bkad * 2);

    float acc[4][4][4];
#pragma unroll
    for (int mt = 0; mt < 4; mt++)
#pragma unroll
        for (int nt = 0; nt < 4; nt++)
#pragma unroll
            for (int q = 0; q < 4; q++) acc[mt][nt][q] = 0.f;

    const int NC = DM / BK;   // 16

    // ---- stage loader ----
    auto load_stage = [&](int s, int k0) {
        uint32_t sb = sbase + s * STAGE_B;
#pragma unroll
        for (int j = 0; j < 4; j++) {
            int ci  = tid + j * 256;          // 0..1023
            int row = ci >> 3, kc = ci & 7;
            uint32_t d0 = sb + row * SROWB + kc * 16;
            size_t ax = (size_t)rows_s[row] * DM + k0 + kc * 8;
            cpa16(d0,                 g_x_hi + ax);
            cpa16(d0 + TILE_B,        g_x_lo + ax);
            size_t bx = ((size_t)e * DE + n0 + row) * DM + k0 + kc * 8;
            cpa16(d0 + 2 * TILE_B,    g_w1t_hi + bx);
            cpa16(d0 + 3 * TILE_B,    g_w1t_lo + bx);
        }
    };

    load_stage(0, 0);
    CP_COMMIT();

    for (int c = 0; c < NC; c++) {
        if (c + 1 < NC) load_stage((c + 1) & 1, (c + 1) * BK);
        CP_COMMIT();
        CP_WAIT1();
        __syncthreads();

        uint32_t sb = sbase + (c & 1) * STAGE_B;
#pragma unroll
        for (int ks = 0; ks < 4; ks++) {
            uint32_t ah[4][4], al[4][4], bh[4][2], bl[4][2];
#pragma unroll
            for (int mt = 0; mt < 4; mt++) {
                uint32_t aa = sb + a_off + mt * 16 * SROWB + ks * 32;
                LDMX4(ah[mt][0], ah[mt][1], ah[mt][2], ah[mt][3], aa);
                LDMX4(al[mt][0], al[mt][1], al[mt][2], al[mt][3], aa + TILE_B);
            }
#pragma unroll
            for (int p = 0; p < 2; p++) {
                uint32_t ba = sb + 2 * TILE_B + b_off + p * 16 * SROWB + ks * 32;
                uint32_t t0, t1, t2, t3;
                LDMX4(t0, t1, t2, t3, ba);
                bh[2 * p][0] = t0; bh[2 * p][1] = t1;
                bh[2 * p + 1][0] = t2; bh[2 * p + 1][1] = t3;
                LDMX4(t0, t1, t2, t3, ba + TILE_B);
                bl[2 * p][0] = t0; bl[2 * p][1] = t1;
                bl[2 * p + 1][0] = t2; bl[2 * p + 1][1] = t3;
            }
#pragma unroll
            for (int mt = 0; mt < 4; mt++)
#pragma unroll
                for (int nt = 0; nt < 4; nt++) {
                    MMA(acc[mt][nt], ah[mt], bh[nt]);
                    MMA(acc[mt][nt], ah[mt], bl[nt]);
                    MMA(acc[mt][nt], al[mt], bh[nt]);
                }
        }
        __syncthreads();
    }

    // ---- epilogue: bias + gelu, split to bf16 hi/lo ----
    int r = lane >> 2, cp = (lane & 3) * 2;
#pragma unroll
    for (int mt = 0; mt < 4; mt++)
#pragma unroll
        for (int half = 0; half < 2; half++) {
            int m = m0 + warpM * 64 + mt * 16 + r + half * 8;
            if (m >= cnt) continue;
            size_t base = ((size_t)e * NTOK + m) * DE;
#pragma unroll
            for (int nt = 0; nt < 4; nt++) {
                int nn = n0 + warpN * 32 + nt * 8 + cp;
                float v0 = acc[mt][nt][half * 2 + 0] + b1[e * DE + nn];
                float v1 = acc[mt][nt][half * 2 + 1] + b1[e * DE + nn + 1];
                v0 = 0.5f * v0 * (1.0f + erff(v0 * 0.7071067811865476f));
                v1 = 0.5f * v1 * (1.0f + erff(v1 * 0.7071067811865476f));
                unsigned h0, l0, h1, l1;
                split1(v0, h0, l0); split1(v1, h1, l1);
                *(unsigned*)((__nv_bfloat16*)g_h_hi + base + nn) = h0 | (h1 << 16);
                *(unsigned*)((__nv_bfloat16*)g_h_lo + base + nn) = l0 | (l1 << 16);
            }
        }
}

// ============================================================
// 5) FF2: out[tok] += gate * (h @ w2[e] + b2[e])
//    grid (NTOK/128, DM/128, NE), block 256
// ============================================================
__global__ __launch_bounds__(256, 1) void ff2_mma(const float* __restrict__ b2,
                                                  float* __restrict__ out) {
    extern __shared__ char dsm[];

    int e   = blockIdx.z;
    int cnt = g_count[e];
    int m0  = blockIdx.x * 128;
    if (m0 >= cnt) return;
    int n0  = blockIdx.y * 128;
    int tid = threadIdx.x, lane = tid & 31, wid = tid >> 5;
    int warpM = wid >> 2, warpN = wid & 3;

    uint32_t sbase = smem_u32(dsm);

    int arow = lane & 15;
    int akad = (lane >> 4) << 3;
    int brow = ((lane & 16) >> 1) | (lane & 7);
    int bkad = lane & 8;
    uint32_t a_off = (uint32_t)((warpM * 64 + arow) * SROWB + akad * 2);
    uint32_t b_off = (uint32_t)((warpN * 32 + brow) * SROWB + bkad * 2);

    float acc[4][4][4];
#pragma unroll
    for (int mt = 0; mt < 4; mt++)
#pragma unroll
        for (int nt = 0; nt < 4; nt++)
#pragma unroll
            for (int q = 0; q < 4; q++) acc[mt][nt][q] = 0.f;

    const int NC = DE / BK;   // 8

    auto load_stage = [&](int s, int k0) {
        uint32_t sb = sbase + s * STAGE_B;
#pragma unroll
        for (int j = 0; j < 4; j++) {
            int ci  = tid + j * 256;
            int row = ci >> 3, kc = ci & 7;
            uint32_t d0 = sb + row * SROWB + kc * 16;
            size_t ax = ((size_t)e * NTOK + m0 + row) * DE + k0 + kc * 8;
            cpa16(d0,                 g_h_hi + ax);
            cpa16(d0 + TILE_B,        g_h_lo + ax);
            size_t bx = ((size_t)e * DM + n0 + row) * DE + k0 + kc * 8;
            cpa16(d0 + 2 * TILE_B,    g_w2t_hi + bx);
            cpa16(d0 + 3 * TILE_B,    g_w2t_lo + bx);
        }
    };

    load_stage(0, 0);
    CP_COMMIT();

    for (int c = 0; c < NC; c++) {
        if (c + 1 < NC) load_stage((c + 1) & 1, (c + 1) * BK);
        CP_COMMIT();
        CP_WAIT1();
        __syncthreads();

        uint32_t sb = sbase + (c & 1) * STAGE_B;
#pragma unroll
        for (int ks = 0; ks < 4; ks++) {
            uint32_t ah[4][4], al[4][4], bh[4][2], bl[4][2];
#pragma unroll
            for (int mt = 0; mt < 4; mt++) {
                uint32_t aa = sb + a_off + mt * 16 * SROWB + ks * 32;
                LDMX4(ah[mt][0], ah[mt][1], ah[mt][2], ah[mt][3], aa);
                LDMX4(al[mt][0], al[mt][1], al[mt][2], al[mt][3], aa + TILE_B);
            }
#pragma unroll
            for (int p = 0; p < 2; p++) {
                uint32_t ba = sb + 2 * TILE_B + b_off + p * 16 * SROWB + ks * 32;
                uint32_t t0, t1, t2, t3;
                LDMX4(t0, t1, t2, t3, ba);
                bh[2 * p][0] = t0; bh[2 * p][1] = t1;
                bh[2 * p + 1][0] = t2; bh[2 * p + 1][1] = t3;
                LDMX4(t0, t1, t2, t3, ba + TILE_B);
                bl[2 * p][0] = t0; bl[2 * p][1] = t1;
                bl[2 * p + 1][0] = t2; bl[2 * p + 1][1] = t3;
            }
#pragma unroll
            for (int mt = 0; mt < 4; mt++)
#pragma unroll
                for (int nt = 0; nt < 4; nt++) {
                    MMA(acc[mt][nt], ah[mt], bh[nt]);
                    MMA(acc[mt][nt], ah[mt], bl[nt]);
                    MMA(acc[mt][nt], al[mt], bh[nt]);
                }
        }
        __syncthreads();
    }

    // ---- epilogue: gate * (acc + b2) -> atomic add into out ----
    int r = lane >> 2, cp = (lane & 3) * 2;
#pragma unroll
    for (int mt = 0; mt < 4; mt++)
#pragma unroll
        for (int half = 0; half < 2; half++) {
            int m = m0 + warpM * 64 + mt * 16 + r + half * 8;
            if (m >= cnt) continue;
            int   tok  = g_tok [e * NTOK + m];
            float gate = g_gate[e * NTOK + m];
            float* orow = out + (size_t)tok * DM;
#pragma unroll
            for (int nt = 0; nt < 4; nt++) {
                int nn = n0 + warpN * 32 + nt * 8 + cp;
                float v0 = gate * (acc[mt][nt][half * 2 + 0] + b2[e * DM + nn]);
                float v1 = gate * (acc[mt][nt][half * 2 + 1] + b2[e * DM + nn + 1]);
                atomicAdd(&orow[nn],     v0);
                atomicAdd(&orow[nn + 1], v1);
            }
        }
}

// ============================================================
// launcher
// ============================================================
extern "C" void kernel_launch(void* const* d_in, const int* in_sizes, int n_in,
                              void* d_out, int out_size) {
    const float* x         = (const float*)d_in[0];
    const float* w1        = (const float*)d_in[1];
    const float* b1        = (const float*)d_in[2];
    const float* w2        = (const float*)d_in[3];
    const float* b2        = (const float*)d_in[4];
    const float* centroids = (const float*)d_in[5];
    const float* w_route   = (const float*)d_in[6];
    float* out = (float*)d_out;

    static int configured = 0;
    if (!configured) {
        cudaFuncSetAttribute(ff1_mma, cudaFuncAttributeMaxDynamicSharedMemorySize, DYN_SMEM);
        cudaFuncSetAttribute(ff2_mma, cudaFuncAttributeMaxDynamicSharedMemorySize, DYN_SMEM);
        configured = 1;
    }

    zero_kernel   <<<(NTOK * DM) / (256 * 4), 256>>>(out);
    prep_x_kernel <<<(NTOK * DM) / (256 * 4), 256>>>(x);
    prep_w1_kernel<<<dim3(DE / 32, DM / 32, NE), dim3(32, 8)>>>(w1);
    prep_w2_kernel<<<dim3(DM / 32, DE / 32, NE), dim3(32, 8)>>>(w2);
    route_kernel  <<<NTOK / 4, 128>>>(x, centroids, w_route);
    ff1_mma<<<dim3(NTOK / 128, DE / 128, NE), 256, DYN_SMEM>>>(b1);
    ff2_mma<<<dim3(NTOK / 128, DM / 128, NE), 256, DYN_SMEM>>>(b2, out);
}

// round 7
// speedup vs baseline: 2.4026x; 1.1168x over previous
#include <cuda_runtime.h>
#include <cuda_bf16.h>
#include <stdint.h>
#include <math.h>

#define NTOK 8192          // B*S
#define DM 1024
#define DE 512
#define NE 8

// ---------------- scratch (device globals) ----------------
__device__ int   g_count[NE];
__device__ int   g_tok [NE * NTOK];
__device__ float g_gate[NE * NTOK];
__device__ __nv_bfloat16 g_x_hi[(size_t)NTOK * DM];
__device__ __nv_bfloat16 g_x_lo[(size_t)NTOK * DM];
__device__ __nv_bfloat16 g_h_hi[(size_t)NE * NTOK * DE];
__device__ __nv_bfloat16 g_h_lo[(size_t)NE * NTOK * DE];
__device__ __nv_bfloat16 g_w1t_hi[(size_t)NE * DE * DM];   // [e][n][k] k-major
__device__ __nv_bfloat16 g_w1t_lo[(size_t)NE * DE * DM];
__device__ __nv_bfloat16 g_w2t_hi[(size_t)NE * DM * DE];   // [e][n][k]
__device__ __nv_bfloat16 g_w2t_lo[(size_t)NE * DM * DE];

// ---------------- helpers ----------------
static __device__ __forceinline__ uint32_t smem_u32(const void* p) {
    uint32_t a;
    asm("{ .reg .u64 t; cvta.to.shared.u64 t, %1; cvt.u32.u64 %0, t; }"
        : "=r"(a) : "l"(p));
    return a;
}

static __device__ __forceinline__ void cpa16(uint32_t dst, const void* src) {
    asm volatile("cp.async.cg.shared.global [%0], [%1], 16;" :: "r"(dst), "l"(src));
}
#define CP_COMMIT() asm volatile("cp.async.commit_group;" ::: "memory")
#define CP_WAIT1()  asm volatile("cp.async.wait_group 1;" ::: "memory")

#define LDMX4(r0, r1, r2, r3, addr)                                          \
    asm volatile("ldmatrix.sync.aligned.m8n8.x4.shared.b16 {%0,%1,%2,%3}, [%4];" \
        : "=r"(r0), "=r"(r1), "=r"(r2), "=r"(r3) : "r"(addr))

#define MMA(ac, a, b)                                                        \
    asm volatile("mma.sync.aligned.m16n8k16.row.col.f32.bf16.bf16.f32 "      \
        "{%0,%1,%2,%3}, {%4,%5,%6,%7}, {%8,%9}, {%0,%1,%2,%3};"              \
        : "+f"((ac)[0]), "+f"((ac)[1]), "+f"((ac)[2]), "+f"((ac)[3])         \
        : "r"((a)[0]), "r"((a)[1]), "r"((a)[2]), "r"((a)[3]),                \
          "r"((b)[0]), "r"((b)[1]))

static __device__ __forceinline__ void split1(float v, unsigned& h, unsigned& l) {
    __nv_bfloat16 bh = __float2bfloat16_rn(v);
    float r = v - __bfloat162float(bh);
    __nv_bfloat16 bl = __float2bfloat16_rn(r);
    h = (unsigned)__bfloat16_as_ushort(bh);
    l = (unsigned)__bfloat16_as_ushort(bl);
}

// ============================================================
// 0) zero output + counters
// ============================================================
__global__ void zero_kernel(float* __restrict__ out) {
    int idx = blockIdx.x * blockDim.x + threadIdx.x;
    ((float4*)out)[idx] = make_float4(0.f, 0.f, 0.f, 0.f);
    if (blockIdx.x == 0 && threadIdx.x < NE) g_count[threadIdx.x] = 0;
}

// ============================================================
// 1) routing: one warp per token
// ============================================================
__global__ void route_kernel(const float* __restrict__ x,
                             const float* __restrict__ centroids,
                             const float* __restrict__ w_route) {
    int gwarp = (blockIdx.x * blockDim.x + threadIdx.x) >> 5;
    int lane  = threadIdx.x & 31;
    if (gwarp >= NTOK) return;
    int tok = gwarp;

    const float4* xr = (const float4*)(x + (size_t)tok * DM);
    float4 xv[8];
#pragma unroll
    for (int u = 0; u < 8; u++) xv[u] = xr[u * 32 + lane];

    float nx = 0.f;
#pragma unroll
    for (int u = 0; u < 8; u++) {
        float4 v = xv[u];
        nx += v.x * v.x + v.y * v.y + v.z * v.z + v.w * v.w;
    }
#pragma unroll
    for (int off = 16; off; off >>= 1) nx += __shfl_xor_sync(0xffffffffu, nx, off);
    float xn = fmaxf(sqrtf(nx), 1e-12f);

    float logits[NE];
#pragma unroll
    for (int e = 0; e < NE; e++) {
        const float4* cr = (const float4*)(centroids + (size_t)e * DM);
        const float4* wr = (const float4*)(w_route   + (size_t)e * DM);
        float sc = 0.f, scc = 0.f, sr = 0.f;
#pragma unroll
        for (int u = 0; u < 8; u++) {
            float4 c = cr[u * 32 + lane];
            float4 w = wr[u * 32 + lane];
            float4 v = xv[u];
            sc  += v.x * c.x + v.y * c.y + v.z * c.z + v.w * c.w;
            scc += c.x * c.x + c.y * c.y + c.z * c.z + c.w * c.w;
            sr  += v.x * w.x + v.y * w.y + v.z * w.z + v.w * w.w;
        }
#pragma unroll
        for (int off = 16; off; off >>= 1) {
            sc  += __shfl_xor_sync(0xffffffffu, sc,  off);
            scc += __shfl_xor_sync(0xffffffffu, scc, off);
            sr  += __shfl_xor_sync(0xffffffffu, sr,  off);
        }
        float cn = fmaxf(sqrtf(scc), 1e-12f);
        logits[e] = sc / (xn * cn) + sr;
    }

    if (lane == 0) {
        int e1 = 0; float l1 = logits[0];
#pragma unroll
        for (int e = 1; e < NE; e++) if (logits[e] > l1) { l1 = logits[e]; e1 = e; }
        int e2 = -1; float l2 = -INFINITY;
#pragma unroll
        for (int e = 0; e < NE; e++) if (e != e1 && logits[e] > l2) { l2 = logits[e]; e2 = e; }
        float b  = expf(l2 - l1);
        float g1 = 1.f / (1.f + b);
        float g2 = b  / (1.f + b);
        int p1 = atomicAdd(&g_count[e1], 1);
        g_tok [e1 * NTOK + p1] = tok;
        g_gate[e1 * NTOK + p1] = g1;
        int p2 = atomicAdd(&g_count[e2], 1);
        g_tok [e2 * NTOK + p2] = tok;
        g_gate[e2 * NTOK + p2] = g2;
    }
}

// ============================================================
// 2) prep: split x -> bf16 hi/lo
// ============================================================
__global__ void prep_x_kernel(const float* __restrict__ x) {
    size_t i = (size_t)blockIdx.x * blockDim.x + threadIdx.x;   // float4 index
    float4 v = ((const float4*)x)[i];
    unsigned h0, l0, h1, l1, h2, l2, h3, l3;
    split1(v.x, h0, l0); split1(v.y, h1, l1);
    split1(v.z, h2, l2); split1(v.w, h3, l3);
    ((uint2*)g_x_hi)[i] = make_uint2(h0 | (h1 << 16), h2 | (h3 << 16));
    ((uint2*)g_x_lo)[i] = make_uint2(l0 | (l1 << 16), l2 | (l3 << 16));
}

// ============================================================
// 3) weight prep: transpose [e][K][N] -> [e][N][K] + bf16 hi/lo split
// ============================================================
static __device__ __forceinline__ void transpose_split_body(
    const float* __restrict__ in, __nv_bfloat16* __restrict__ ohi,
    __nv_bfloat16* __restrict__ olo, int K, int N)
{
    __shared__ float t[32][33];
    int e  = blockIdx.z;
    int n0 = blockIdx.x * 32, k0 = blockIdx.y * 32;
    const float* pin = in + (size_t)e * K * N;
#pragma unroll
    for (int i = 0; i < 4; i++)
        t[threadIdx.y + i * 8][threadIdx.x] =
            pin[(size_t)(k0 + threadIdx.y + i * 8) * N + n0 + threadIdx.x];
    __syncthreads();
#pragma unroll
    for (int i = 0; i < 4; i++) {
        int nl = threadIdx.y + i * 8, kl = threadIdx.x;
        unsigned h, l; split1(t[kl][nl], h, l);
        size_t o = ((size_t)e * N + n0 + nl) * K + k0 + kl;
        ohi[o] = __ushort_as_bfloat16((unsigned short)h);
        olo[o] = __ushort_as_bfloat16((unsigned short)l);
    }
}

__global__ void prep_w1_kernel(const float* __restrict__ w1) {
    transpose_split_body(w1, g_w1t_hi, g_w1t_lo, DM, DE);
}
__global__ void prep_w2_kernel(const float* __restrict__ w2) {
    transpose_split_body(w2, g_w2t_hi, g_w2t_lo, DE, DM);
}

// ============================================================
// GEMM geometry: block 128x128, BK=32, 8 warps (2x4), warp 64x32
// smem row: 32 bf16 data + 8 pad = 40 elems = 80 B
// 2-stage pipeline, 2 CTAs/SM
// ============================================================
#define BK 32
#define SROWB 80
#define TILE_B (128 * SROWB)          // 10240 B per buffer
#define STAGE_B (4 * TILE_B)          // Ahi Alo Bhi Blo = 40960 B
#define DYN_SMEM (2 * STAGE_B)        // 81920 B

// term-grouped MMA core for one k-step: breaks accumulator RAW chains
#define MMA_KSTEP(sb)                                                        \
    do {                                                                     \
        uint32_t ah[4][4], bh[4][2];                                         \
        _Pragma("unroll")                                                    \
        for (int mt = 0; mt < 4; mt++) {                                     \
            uint32_t aa = (sb) + a_off + mt * 16 * SROWB + ks * 32;          \
            LDMX4(ah[mt][0], ah[mt][1], ah[mt][2], ah[mt][3], aa);           \
        }                                                                    \
        _Pragma("unroll")                                                    \
        for (int p = 0; p < 2; p++) {                                        \
            uint32_t ba = (sb) + 2 * TILE_B + b_off + p * 16 * SROWB + ks * 32; \
            uint32_t t0, t1, t2, t3;                                         \
            LDMX4(t0, t1, t2, t3, ba);                                       \
            bh[2 * p][0] = t0; bh[2 * p][1] = t1;                            \
            bh[2 * p + 1][0] = t2; bh[2 * p + 1][1] = t3;                    \
        }                                                                    \
        _Pragma("unroll")                                                    \
        for (int mt = 0; mt < 4; mt++)                                       \
            _Pragma("unroll")                                                \
            for (int nt = 0; nt < 4; nt++) MMA(acc[mt][nt], ah[mt], bh[nt]); \
        uint32_t al[4][4];                                                   \
        _Pragma("unroll")                                                    \
        for (int mt = 0; mt < 4; mt++) {                                     \
            uint32_t aa = (sb) + TILE_B + a_off + mt * 16 * SROWB + ks * 32; \
            LDMX4(al[mt][0], al[mt][1], al[mt][2], al[mt][3], aa);           \
        }                                                                    \
        _Pragma("unroll")                                                    \
        for (int mt = 0; mt < 4; mt++)                                       \
            _Pragma("unroll")                                                \
            for (int nt = 0; nt < 4; nt++) MMA(acc[mt][nt], al[mt], bh[nt]); \
        uint32_t bl[4][2];                                                   \
        _Pragma("unroll")                                                    \
        for (int p = 0; p < 2; p++) {                                        \
            uint32_t ba = (sb) + 3 * TILE_B + b_off + p * 16 * SROWB + ks * 32; \
            uint32_t t0, t1, t2, t3;                                         \
            LDMX4(t0, t1, t2, t3, ba);                                       \
            bl[2 * p][0] = t0; bl[2 * p][1] = t1;                            \
            bl[2 * p + 1][0] = t2; bl[2 * p + 1][1] = t3;                    \
        }                                                                    \
        _Pragma("unroll")                                                    \
        for (int mt = 0; mt < 4; mt++)                                       \
            _Pragma("unroll")                                                \
            for (int nt = 0; nt < 4; nt++) MMA(acc[mt][nt], ah[mt], bl[nt]); \
    } while (0)

// ============================================================
// 4) FF1: h = gelu(gather(x) @ w1[e] + b1[e])
//    grid (NTOK/128, DE/128, NE), block 256, 2 CTA/SM
// ============================================================
__global__ __launch_bounds__(256, 2) void ff1_mma(const float* __restrict__ b1) {
    extern __shared__ char dsm[];
    __shared__ int rows_s[128];

    int e   = blockIdx.z;
    int cnt = g_count[e];
    int m0  = blockIdx.x * 128;
    if (m0 >= cnt) return;
    int n0  = blockIdx.y * 128;
    int tid = threadIdx.x, lane = tid & 31, wid = tid >> 5;
    int warpM = wid >> 2, warpN = wid & 3;

    if (tid < 128) {
        int m = m0 + tid;
        rows_s[tid] = (m < cnt) ? g_tok[e * NTOK + m] : 0;
    }
    __syncthreads();

    uint32_t sbase = smem_u32(dsm);

    int arow = lane & 15;
    int akad = (lane >> 4) << 3;
    int brow = ((lane & 16) >> 1) | (lane & 7);
    int bkad = lane & 8;
    uint32_t a_off = (uint32_t)((warpM * 64 + arow) * SROWB + akad * 2);
    uint32_t b_off = (uint32_t)((warpN * 32 + brow) * SROWB + bkad * 2);

    float acc[4][4][4];
#pragma unroll
    for (int mt = 0; mt < 4; mt++)
#pragma unroll
        for (int nt = 0; nt < 4; nt++)
#pragma unroll
            for (int q = 0; q < 4; q++) acc[mt][nt][q] = 0.f;

    const int NC = DM / BK;   // 32

    // per-stage: 4 tiles x 128 rows x 2 chunks(16B) -> 2 passes of 256 thr per array pair
    auto load_stage = [&](int s, int k0) {
        uint32_t sb = sbase + s * STAGE_B;
#pragma unroll
        for (int j = 0; j < 2; j++) {
            int ci  = tid + j * 256;          // 0..511
            int row = ci >> 2, kc = ci & 3;
            uint32_t d0 = sb + row * SROWB + kc * 16;
            size_t ax = (size_t)rows_s[row] * DM + k0 + kc * 8;
            cpa16(d0,              g_x_hi + ax);
            cpa16(d0 + TILE_B,     g_x_lo + ax);
            size_t bx = ((size_t)e * DE + n0 + row) * DM + k0 + kc * 8;
            cpa16(d0 + 2 * TILE_B, g_w1t_hi + bx);
            cpa16(d0 + 3 * TILE_B, g_w1t_lo + bx);
        }
    };

    load_stage(0, 0);
    CP_COMMIT();

    for (int c = 0; c < NC; c++) {
        if (c + 1 < NC) load_stage((c + 1) & 1, (c + 1) * BK);
        CP_COMMIT();
        CP_WAIT1();
        __syncthreads();
        uint32_t sb = sbase + (c & 1) * STAGE_B;
#pragma unroll
        for (int ks = 0; ks < 2; ks++) { MMA_KSTEP(sb); }
        __syncthreads();
    }

    // ---- epilogue: bias + gelu, split to bf16 hi/lo ----
    int r = lane >> 2, cp = (lane & 3) * 2;
#pragma unroll
    for (int mt = 0; mt < 4; mt++)
#pragma unroll
        for (int half = 0; half < 2; half++) {
            int m = m0 + warpM * 64 + mt * 16 + r + half * 8;
            if (m >= cnt) continue;
            size_t base = ((size_t)e * NTOK + m) * DE;
#pragma unroll
            for (int nt = 0; nt < 4; nt++) {
                int nn = n0 + warpN * 32 + nt * 8 + cp;
                float v0 = acc[mt][nt][half * 2 + 0] + b1[e * DE + nn];
                float v1 = acc[mt][nt][half * 2 + 1] + b1[e * DE + nn + 1];
                v0 = 0.5f * v0 * (1.0f + erff(v0 * 0.7071067811865476f));
                v1 = 0.5f * v1 * (1.0f + erff(v1 * 0.7071067811865476f));
                unsigned h0, l0, h1, l1;
                split1(v0, h0, l0); split1(v1, h1, l1);
                *(unsigned*)((__nv_bfloat16*)g_h_hi + base + nn) = h0 | (h1 << 16);
                *(unsigned*)((__nv_bfloat16*)g_h_lo + base + nn) = l0 | (l1 << 16);
            }
        }
}

// ============================================================
// 5) FF2: out[tok] += gate * (h @ w2[e] + b2[e])
//    grid (NTOK/128, DM/128, NE), block 256, 2 CTA/SM
// ============================================================
__global__ __launch_bounds__(256, 2) void ff2_mma(const float* __restrict__ b2,
                                                  float* __restrict__ out) {
    extern __shared__ char dsm[];

    int e   = blockIdx.z;
    int cnt = g_count[e];
    int m0  = blockIdx.x * 128;
    if (m0 >= cnt) return;
    int n0  = blockIdx.y * 128;
    int tid = threadIdx.x, lane = tid & 31, wid = tid >> 5;
    int warpM = wid >> 2, warpN = wid & 3;

    uint32_t sbase = smem_u32(dsm);

    int arow = lane & 15;
    int akad = (lane >> 4) << 3;
    int brow = ((lane & 16) >> 1) | (lane & 7);
    int bkad = lane & 8;
    uint32_t a_off = (uint32_t)((warpM * 64 + arow) * SROWB + akad * 2);
    uint32_t b_off = (uint32_t)((warpN * 32 + brow) * SROWB + bkad * 2);

    float acc[4][4][4];
#pragma unroll
    for (int mt = 0; mt < 4; mt++)
#pragma unroll
        for (int nt = 0; nt < 4; nt++)
#pragma unroll
            for (int q = 0; q < 4; q++) acc[mt][nt][q] = 0.f;

    const int NC = DE / BK;   // 16

    auto load_stage = [&](int s, int k0) {
        uint32_t sb = sbase + s * STAGE_B;
#pragma unroll
        for (int j = 0; j < 2; j++) {
            int ci  = tid + j * 256;
            int row = ci >> 2, kc = ci & 3;
            uint32_t d0 = sb + row * SROWB + kc * 16;
            size_t ax = ((size_t)e * NTOK + m0 + row) * DE + k0 + kc * 8;
            cpa16(d0,              g_h_hi + ax);
            cpa16(d0 + TILE_B,     g_h_lo + ax);
            size_t bx = ((size_t)e * DM + n0 + row) * DE + k0 + kc * 8;
            cpa16(d0 + 2 * TILE_B, g_w2t_hi + bx);
            cpa16(d0 + 3 * TILE_B, g_w2t_lo + bx);
        }
    };

    load_stage(0, 0);
    CP_COMMIT();

    for (int c = 0; c < NC; c++) {
        if (c + 1 < NC) load_stage((c + 1) & 1, (c + 1) * BK);
        CP_COMMIT();
        CP_WAIT1();
        __syncthreads();
        uint32_t sb = sbase + (c & 1) * STAGE_B;
#pragma unroll
        for (int ks = 0; ks < 2; ks++) { MMA_KSTEP(sb); }
        __syncthreads();
    }

    // ---- epilogue: gate * (acc + b2) -> atomic add into out ----
    int r = lane >> 2, cp = (lane & 3) * 2;
#pragma unroll
    for (int mt = 0; mt < 4; mt++)
#pragma unroll
        for (int half = 0; half < 2; half++) {
            int m = m0 + warpM * 64 + mt * 16 + r + half * 8;
            if (m >= cnt) continue;
            int   tok  = g_tok [e * NTOK + m];
            float gate = g_gate[e * NTOK + m];
            float* orow = out + (size_t)tok * DM;
#pragma unroll
            for (int nt = 0; nt < 4; nt++) {
                int nn = n0 + warpN * 32 + nt * 8 + cp;
                float v0 = gate * (acc[mt][nt][half * 2 + 0] + b2[e * DM + nn]);
                float v1 = gate * (acc[mt][nt][half * 2 + 1] + b2[e * DM + nn + 1]);
                atomicAdd(&orow[nn],     v0);
                atomicAdd(&orow[nn + 1], v1);
            }
        }
}

// ============================================================
// launcher: fork independent prep kernels onto side streams
// ============================================================
extern "C" void kernel_launch(void* const* d_in, const int* in_sizes, int n_in,
                              void* d_out, int out_size) {
    const float* x         = (const float*)d_in[0];
    const float* w1        = (const float*)d_in[1];
    const float* b1        = (const float*)d_in[2];
    const float* w2        = (const float*)d_in[3];
    const float* b2        = (const float*)d_in[4];
    const float* centroids = (const float*)d_in[5];
    const float* w_route   = (const float*)d_in[6];
    float* out = (float*)d_out;

    static cudaStream_t sA = nullptr, sB = nullptr;
    static cudaEvent_t evFork, evA, evB;
    if (!sA) {
        cudaStreamCreateWithFlags(&sA, cudaStreamNonBlocking);
        cudaStreamCreateWithFlags(&sB, cudaStreamNonBlocking);
        cudaEventCreateWithFlags(&evFork, cudaEventDisableTiming);
        cudaEventCreateWithFlags(&evA, cudaEventDisableTiming);
        cudaEventCreateWithFlags(&evB, cudaEventDisableTiming);
        cudaFuncSetAttribute(ff1_mma, cudaFuncAttributeMaxDynamicSharedMemorySize, DYN_SMEM);
        cudaFuncSetAttribute(ff2_mma, cudaFuncAttributeMaxDynamicSharedMemorySize, DYN_SMEM);
    }

    // main stream: zero -> route (route needs g_count zeroed)
    zero_kernel<<<(NTOK * DM) / (256 * 4), 256>>>(out);
    cudaEventRecord(evFork, 0);

    // side stream A: x split + w1 prep ; side stream B: w2 prep
    cudaStreamWaitEvent(sA, evFork, 0);
    cudaStreamWaitEvent(sB, evFork, 0);
    prep_x_kernel <<<(NTOK * DM) / (256 * 4), 256, 0, sA>>>(x);
    prep_w1_kernel<<<dim3(DE / 32, DM / 32, NE), dim3(32, 8), 0, sA>>>(w1);
    prep_w2_kernel<<<dim3(DM / 32, DE / 32, NE), dim3(32, 8), 0, sB>>>(w2);
    cudaEventRecord(evA, sA);
    cudaEventRecord(evB, sB);

    route_kernel<<<NTOK / 4, 128>>>(x, centroids, w_route);

    // join before GEMMs
    cudaStreamWaitEvent(0, evA, 0);
    cudaStreamWaitEvent(0, evB, 0);
    ff1_mma<<<dim3(NTOK / 128, DE / 128, NE), 256, DYN_SMEM>>>(b1);
    ff2_mma<<<dim3(NTOK / 128, DM / 128, NE), 256, DYN_SMEM>>>(b2, out);
}

// round 10
// speedup vs baseline: 2.9729x; 1.2374x over previous
#include <cuda_runtime.h>
#include <cuda_fp16.h>
#include <stdint.h>
#include <math.h>

#define NTOK 8192          // B*S
#define DM 1024
#define DE 512
#define NE 8

// ---------------- scratch (device globals) ----------------
__device__ int   g_count[NE];
__device__ int   g_tok [NE * NTOK];
__device__ float g_gate[NE * NTOK];
__device__ __half g_x_hi[(size_t)NTOK * DM];
__device__ __half g_x_lo[(size_t)NTOK * DM];
__device__ __half g_h_hi[(size_t)NE * NTOK * DE];
__device__ __half g_h_lo[(size_t)NE * NTOK * DE];
__device__ __half g_w1t[(size_t)NE * DE * DM];   // [e][n][k] k-major, fp16
__device__ __half g_w2t[(size_t)NE * DM * DE];   // [e][n][k] fp16

// ---------------- helpers ----------------
static __device__ __forceinline__ uint32_t smem_u32(const void* p) {
    uint32_t a;
    asm("{ .reg .u64 t; cvta.to.shared.u64 t, %1; cvt.u32.u64 %0, t; }"
        : "=r"(a) : "l"(p));
    return a;
}

static __device__ __forceinline__ void cpa16(uint32_t dst, const void* src) {
    asm volatile("cp.async.cg.shared.global [%0], [%1], 16;" :: "r"(dst), "l"(src));
}
#define CP_COMMIT() asm volatile("cp.async.commit_group;" ::: "memory")
#define CP_WAIT2()  asm volatile("cp.async.wait_group 2;" ::: "memory")

#define LDMX4(r0, r1, r2, r3, addr)                                          \
    asm volatile("ldmatrix.sync.aligned.m8n8.x4.shared.b16 {%0,%1,%2,%3}, [%4];" \
        : "=r"(r0), "=r"(r1), "=r"(r2), "=r"(r3) : "r"(addr))

#define MMA(ac, a, b)                                                        \
    asm volatile("mma.sync.aligned.m16n8k16.row.col.f32.f16.f16.f32 "        \
        "{%0,%1,%2,%3}, {%4,%5,%6,%7}, {%8,%9}, {%0,%1,%2,%3};"              \
        : "+f"((ac)[0]), "+f"((ac)[1]), "+f"((ac)[2]), "+f"((ac)[3])         \
        : "r"((a)[0]), "r"((a)[1]), "r"((a)[2]), "r"((a)[3]),                \
          "r"((b)[0]), "r"((b)[1]))

static __device__ __forceinline__ void split1h(float v, unsigned& h, unsigned& l) {
    __half hh = __float2half_rn(v);
    float r = v - __half2float(hh);
    __half hl = __float2half_rn(r);
    h = (unsigned)__half_as_ushort(hh);
    l = (unsigned)__half_as_ushort(hl);
}

// ============================================================
// 0) zero output + counters
// ============================================================
__global__ void zero_kernel(float* __restrict__ out) {
    int idx = blockIdx.x * blockDim.x + threadIdx.x;
    ((float4*)out)[idx] = make_float4(0.f, 0.f, 0.f, 0.f);
    if (blockIdx.x == 0 && threadIdx.x < NE) g_count[threadIdx.x] = 0;
}

// ============================================================
// 1) merged prep: x-split (fp16 hi/lo) + w1/w2 transpose to fp16
//    grid 16384 x 256: [0,8192) x-split, [8192,12288) w1, [12288,16384) w2
// ============================================================
#define XB 8192
__global__ void prep_all(const float* __restrict__ x,
                         const float* __restrict__ w1,
                         const float* __restrict__ w2) {
    __shared__ float t[32][33];
    int b = blockIdx.x, tid = threadIdx.x;

    if (b < XB) {
        size_t i = (size_t)b * 256 + tid;   // float4 index
        float4 v = ((const float4*)x)[i];
        unsigned h0, l0, h1, l1, h2, l2, h3, l3;
        split1h(v.x, h0, l0); split1h(v.y, h1, l1);
        split1h(v.z, h2, l2); split1h(v.w, h3, l3);
        ((uint2*)g_x_hi)[i] = make_uint2(h0 | (h1 << 16), h2 | (h3 << 16));
        ((uint2*)g_x_lo)[i] = make_uint2(l0 | (l1 << 16), l2 | (l3 << 16));
        return;
    }

    const float* in;
    __half* outp;
    int K, N, nblk;
    if (b < XB + 4096) { b -= XB;        in = w1; outp = g_w1t; K = DM; N = DE; nblk = 16; }
    else               { b -= XB + 4096; in = w2; outp = g_w2t; K = DE; N = DM; nblk = 32; }

    int per_e = nblk * (K / 32);
    int e   = b / per_e;
    int rem = b % per_e;
    int n0  = (rem % nblk) * 32;
    int k0  = (rem / nblk) * 32;
    int tx  = tid & 31, ty = tid >> 5;

    const float* pin = in + (size_t)e * K * N;
#pragma unroll
    for (int i = 0; i < 4; i++)
        t[ty + i * 8][tx] = pin[(size_t)(k0 + ty + i * 8) * N + n0 + tx];
    __syncthreads();
#pragma unroll
    for (int i = 0; i < 4; i++) {
        int nl = ty + i * 8, kl = tx;
        outp[((size_t)e * N + n0 + nl) * K + k0 + kl] = __float2half_rn(t[kl][nl]);
    }
}

// ============================================================
// 2) routing: one warp per token
// ============================================================
__global__ void route_kernel(const float* __restrict__ x,
                             const float* __restrict__ centroids,
                             const float* __restrict__ w_route) {
    int gwarp = (blockIdx.x * blockDim.x + threadIdx.x) >> 5;
    int lane  = threadIdx.x & 31;
    if (gwarp >= NTOK) return;
    int tok = gwarp;

    const float4* xr = (const float4*)(x + (size_t)tok * DM);
    float4 xv[8];
#pragma unroll
    for (int u = 0; u < 8; u++) xv[u] = xr[u * 32 + lane];

    float nx = 0.f;
#pragma unroll
    for (int u = 0; u < 8; u++) {
        float4 v = xv[u];
        nx += v.x * v.x + v.y * v.y + v.z * v.z + v.w * v.w;
    }
#pragma unroll
    for (int off = 16; off; off >>= 1) nx += __shfl_xor_sync(0xffffffffu, nx, off);
    float xn = fmaxf(sqrtf(nx), 1e-12f);

    float logits[NE];
#pragma unroll
    for (int e = 0; e < NE; e++) {
        const float4* cr = (const float4*)(centroids + (size_t)e * DM);
        const float4* wr = (const float4*)(w_route   + (size_t)e * DM);
        float sc = 0.f, scc = 0.f, sr = 0.f;
#pragma unroll
        for (int u = 0; u < 8; u++) {
            float4 c = cr[u * 32 + lane];
            float4 w = wr[u * 32 + lane];
            float4 v = xv[u];
            sc  += v.x * c.x + v.y * c.y + v.z * c.z + v.w * c.w;
            scc += c.x * c.x + c.y * c.y + c.z * c.z + c.w * c.w;
            sr  += v.x * w.x + v.y * w.y + v.z * w.z + v.w * w.w;
        }
#pragma unroll
        for (int off = 16; off; off >>= 1) {
            sc  += __shfl_xor_sync(0xffffffffu, sc,  off);
            scc += __shfl_xor_sync(0xffffffffu, scc, off);
            sr  += __shfl_xor_sync(0xffffffffu, sr,  off);
        }
        float cn = fmaxf(sqrtf(scc), 1e-12f);
        logits[e] = sc / (xn * cn) + sr;
    }

    if (lane == 0) {
        int e1 = 0; float l1 = logits[0];
#pragma unroll
        for (int e = 1; e < NE; e++) if (logits[e] > l1) { l1 = logits[e]; e1 = e; }
        int e2 = -1; float l2 = -INFINITY;
#pragma unroll
        for (int e = 0; e < NE; e++) if (e != e1 && logits[e] > l2) { l2 = logits[e]; e2 = e; }
        float b  = expf(l2 - l1);
        float g1 = 1.f / (1.f + b);
        float g2 = b  / (1.f + b);
        int p1 = atomicAdd(&g_count[e1], 1);
        g_tok [e1 * NTOK + p1] = tok;
        g_gate[e1 * NTOK + p1] = g1;
        int p2 = atomicAdd(&g_count[e2], 1);
        g_tok [e2 * NTOK + p2] = tok;
        g_gate[e2 * NTOK + p2] = g2;
    }
}

// ============================================================
// GEMM geometry: block 128x128, BK=32, 8 warps (2x4), warp 64x32
// fp16 2-term split: acc += Ahi*B + Alo*B
// smem row: 32 fp16 + 8 pad = 80 B; 3 tiles (Ahi, Alo, B); 3 stages
// ============================================================
#define BK 32
#define SROWB 80
#define TILE_B (128 * SROWB)          // 10240 B
#define STAGE_B (3 * TILE_B)          // 30720 B
#define DYN_SMEM (3 * STAGE_B)        // 92160 B, 2 CTA/SM

#define MMA_KSTEP(sb)                                                        \
    do {                                                                     \
        uint32_t ah[4][4], bh[4][2];                                         \
        _Pragma("unroll")                                                    \
        for (int mt = 0; mt < 4; mt++) {                                     \
            uint32_t aa = (sb) + a_off + mt * 16 * SROWB + ks * 32;          \
            LDMX4(ah[mt][0], ah[mt][1], ah[mt][2], ah[mt][3], aa);           \
        }                                                                    \
        _Pragma("unroll")                                                    \
        for (int p = 0; p < 2; p++) {                                        \
            uint32_t ba = (sb) + 2 * TILE_B + b_off + p * 16 * SROWB + ks * 32; \
            uint32_t t0, t1, t2, t3;                                         \
            LDMX4(t0, t1, t2, t3, ba);                                       \
            bh[2 * p][0] = t0; bh[2 * p][1] = t1;                            \
            bh[2 * p + 1][0] = t2; bh[2 * p + 1][1] = t3;                    \
        }                                                                    \
        _Pragma("unroll")                                                    \
        for (int mt = 0; mt < 4; mt++)                                       \
            _Pragma("unroll")                                                \
            for (int nt = 0; nt < 4; nt++) MMA(acc[mt][nt], ah[mt], bh[nt]); \
        uint32_t al[4][4];                                                   \
        _Pragma("unroll")                                                    \
        for (int mt = 0; mt < 4; mt++) {                                     \
            uint32_t aa = (sb) + TILE_B + a_off + mt * 16 * SROWB + ks * 32; \
            LDMX4(al[mt][0], al[mt][1], al[mt][2], al[mt][3], aa);           \
        }                                                                    \
        _Pragma("unroll")                                                    \
        for (int mt = 0; mt < 4; mt++)                                       \
            _Pragma("unroll")                                                \
            for (int nt = 0; nt < 4; nt++) MMA(acc[mt][nt], al[mt], bh[nt]); \
    } while (0)

// ============================================================
// 3) FF1: h = gelu(gather(x) @ w1[e] + b1[e])
// ============================================================
__global__ __launch_bounds__(256, 2) void ff1_mma(const float* __restrict__ b1) {
    extern __shared__ char dsm[];
    __shared__ int rows_s[128];

    int e   = blockIdx.z;
    int cnt = g_count[e];
    int m0  = blockIdx.x * 128;
    if (m0 >= cnt) return;
    int n0  = blockIdx.y * 128;
    int tid = threadIdx.x, lane = tid & 31, wid = tid >> 5;
    int warpM = wid >> 2, warpN = wid & 3;

    if (tid < 128) {
        int m = m0 + tid;
        rows_s[tid] = (m < cnt) ? g_tok[e * NTOK + m] : 0;
    }
    __syncthreads();

    uint32_t sbase = smem_u32(dsm);

    int arow = lane & 15;
    int akad = (lane >> 4) << 3;
    int brow = ((lane & 16) >> 1) | (lane & 7);
    int bkad = lane & 8;
    uint32_t a_off = (uint32_t)((warpM * 64 + arow) * SROWB + akad * 2);
    uint32_t b_off = (uint32_t)((warpN * 32 + brow) * SROWB + bkad * 2);

    float acc[4][4][4];
#pragma unroll
    for (int mt = 0; mt < 4; mt++)
#pragma unroll
        for (int nt = 0; nt < 4; nt++)
#pragma unroll
            for (int q = 0; q < 4; q++) acc[mt][nt][q] = 0.f;

    const int NC = DM / BK;   // 32

    auto load_stage = [&](int s, int k0) {
        uint32_t sb = sbase + s * STAGE_B;
#pragma unroll
        for (int j = 0; j < 2; j++) {
            int ci  = tid + j * 256;          // 0..511
            int row = ci >> 2, kc = ci & 3;
            uint32_t d0 = sb + row * SROWB + kc * 16;
            size_t ax = (size_t)rows_s[row] * DM + k0 + kc * 8;
            cpa16(d0,              g_x_hi + ax);
            cpa16(d0 + TILE_B,     g_x_lo + ax);
            size_t bx = ((size_t)e * DE + n0 + row) * DM + k0 + kc * 8;
            cpa16(d0 + 2 * TILE_B, g_w1t + bx);
        }
    };

    load_stage(0, 0); CP_COMMIT();
    load_stage(1, BK); CP_COMMIT();

    int sc = 0;
    for (int c = 0; c < NC; c++) {
        if (c + 2 < NC) {
            int sn = sc + 2; if (sn >= 3) sn -= 3;
            load_stage(sn, (c + 2) * BK);
        }
        CP_COMMIT();
        CP_WAIT2();
        __syncthreads();
        uint32_t sb = sbase + sc * STAGE_B;
#pragma unroll
        for (int ks = 0; ks < 2; ks++) { MMA_KSTEP(sb); }
        __syncthreads();
        if (++sc == 3) sc = 0;
    }

    // ---- epilogue: bias + gelu, split to fp16 hi/lo ----
    int r = lane >> 2, cp = (lane & 3) * 2;
#pragma unroll
    for (int mt = 0; mt < 4; mt++)
#pragma unroll
        for (int half = 0; half < 2; half++) {
            int m = m0 + warpM * 64 + mt * 16 + r + half * 8;
            if (m >= cnt) continue;
            size_t base = ((size_t)e * NTOK + m) * DE;
#pragma unroll
            for (int nt = 0; nt < 4; nt++) {
                int nn = n0 + warpN * 32 + nt * 8 + cp;
                float v0 = acc[mt][nt][half * 2 + 0] + b1[e * DE + nn];
                float v1 = acc[mt][nt][half * 2 + 1] + b1[e * DE + nn + 1];
                v0 = 0.5f * v0 * (1.0f + erff(v0 * 0.7071067811865476f));
                v1 = 0.5f * v1 * (1.0f + erff(v1 * 0.7071067811865476f));
                unsigned h0, l0, h1, l1;
                split1h(v0, h0, l0); split1h(v1, h1, l1);
                *(unsigned*)((__half*)g_h_hi + base + nn) = h0 | (h1 << 16);
                *(unsigned*)((__half*)g_h_lo + base + nn) = l0 | (l1 << 16);
            }
        }
}

// ============================================================
// 4) FF2: out[tok] += gate * (h @ w2[e] + b2[e])
// ============================================================
__global__ __launch_bounds__(256, 2) void ff2_mma(const float* __restrict__ b2,
                                                  float* __restrict__ out) {
    extern __shared__ char dsm[];

    int e   = blockIdx.z;
    int cnt = g_count[e];
    int m0  = blockIdx.x * 128;
    if (m0 >= cnt) return;
    int n0  = blockIdx.y * 128;
    int tid = threadIdx.x, lane = tid & 31, wid = tid >> 5;
    int warpM = wid >> 2, warpN = wid & 3;

    uint32_t sbase = smem_u32(dsm);

    int arow = lane & 15;
    int akad = (lane >> 4) << 3;
    int brow = ((lane & 16) >> 1) | (lane & 7);
    int bkad = lane & 8;
    uint32_t a_off = (uint32_t)((warpM * 64 + arow) * SROWB + akad * 2);
    uint32_t b_off = (uint32_t)((warpN * 32 + brow) * SROWB + bkad * 2);

    float acc[4][4][4];
#pragma unroll
    for (int mt = 0; mt < 4; mt++)
#pragma unroll
        for (int nt = 0; nt < 4; nt++)
#pragma unroll
            for (int q = 0; q < 4; q++) acc[mt][nt][q] = 0.f;

    const int NC = DE / BK;   // 16

    auto load_stage = [&](int s, int k0) {
        uint32_t sb = sbase + s * STAGE_B;
#pragma unroll
        for (int j = 0; j < 2; j++) {
            int ci  = tid + j * 256;
            int row = ci >> 2, kc = ci & 3;
            uint32_t d0 = sb + row * SROWB + kc * 16;
            size_t ax = ((size_t)e * NTOK + m0 + row) * DE + k0 + kc * 8;
            cpa16(d0,              g_h_hi + ax);
            cpa16(d0 + TILE_B,     g_h_lo + ax);
            size_t bx = ((size_t)e * DM + n0 + row) * DE + k0 + kc * 8;
            cpa16(d0 + 2 * TILE_B, g_w2t + bx);
        }
    };

    load_stage(0, 0); CP_COMMIT();
    load_stage(1, BK); CP_COMMIT();

    int sc = 0;
    for (int c = 0; c < NC; c++) {
        if (c + 2 < NC) {
            int sn = sc + 2; if (sn >= 3) sn -= 3;
            load_stage(sn, (c + 2) * BK);
        }
        CP_COMMIT();
        CP_WAIT2();
        __syncthreads();
        uint32_t sb = sbase + sc * STAGE_B;
#pragma unroll
        for (int ks = 0; ks < 2; ks++) { MMA_KSTEP(sb); }
        __syncthreads();
        if (++sc == 3) sc = 0;
    }

    // ---- epilogue: gate * (acc + b2) -> atomic add into out ----
    int r = lane >> 2, cp = (lane & 3) * 2;
#pragma unroll
    for (int mt = 0; mt < 4; mt++)
#pragma unroll
        for (int half = 0; half < 2; half++) {
            int m = m0 + warpM * 64 + mt * 16 + r + half * 8;
            if (m >= cnt) continue;
            int   tok  = g_tok [e * NTOK + m];
            float gate = g_gate[e * NTOK + m];
            float* orow = out + (size_t)tok * DM;
#pragma unroll
            for (int nt = 0; nt < 4; nt++) {
                int nn = n0 + warpN * 32 + nt * 8 + cp;
                float v0 = gate * (acc[mt][nt][half * 2 + 0] + b2[e * DM + nn]);
                float v1 = gate * (acc[mt][nt][half * 2 + 1] + b2[e * DM + nn + 1]);
                atomicAdd(&orow[nn],     v0);
                atomicAdd(&orow[nn + 1], v1);
            }
        }
}

// ============================================================
// launcher: zero(1), prep_all(2, side stream), route(3), ff1(4), ff2(5)
// ============================================================
extern "C" void kernel_launch(void* const* d_in, const int* in_sizes, int n_in,
                              void* d_out, int out_size) {
    const float* x         = (const float*)d_in[0];
    const float* w1        = (const float*)d_in[1];
    const float* b1        = (const float*)d_in[2];
    const float* w2        = (const float*)d_in[3];
    const float* b2        = (const float*)d_in[4];
    const float* centroids = (const float*)d_in[5];
    const float* w_route   = (const float*)d_in[6];
    float* out = (float*)d_out;

    static cudaStream_t sA = nullptr;
    static cudaEvent_t evFork, evA;
    if (!sA) {
        cudaStreamCreateWithFlags(&sA, cudaStreamNonBlocking);
        cudaEventCreateWithFlags(&evFork, cudaEventDisableTiming);
        cudaEventCreateWithFlags(&evA, cudaEventDisableTiming);
        cudaFuncSetAttribute(ff1_mma, cudaFuncAttributeMaxDynamicSharedMemorySize, DYN_SMEM);
        cudaFuncSetAttribute(ff2_mma, cudaFuncAttributeMaxDynamicSharedMemorySize, DYN_SMEM);
    }

    zero_kernel<<<(NTOK * DM) / (256 * 4), 256>>>(out);
    cudaEventRecord(evFork, 0);

    cudaStreamWaitEvent(sA, evFork, 0);
    prep_all<<<XB + 8192, 256, 0, sA>>>(x, w1, w2);
    cudaEventRecord(evA, sA);

    route_kernel<<<NTOK / 4, 128>>>(x, centroids, w_route);

    cudaStreamWaitEvent(0, evA, 0);
    ff1_mma<<<dim3(NTOK / 128, DE / 128, NE), 256, DYN_SMEM>>>(b1);
    ff2_mma<<<dim3(NTOK / 128, DM / 128, NE), 256, DYN_SMEM>>>(b2, out);
}